// round 6
// baseline (speedup 1.0000x reference)
#include <cuda_runtime.h>
#include <cuda_bf16.h>
#include <cstdint>

#define B_DIM 4096
#define IN_DIM 2048
#define F_DIM 4096

// ---------------------------------------------------------------------------
// Scratch (device globals: no allocation allowed)
// ---------------------------------------------------------------------------
__device__ float          g_xr[B_DIM * IN_DIM];    // rotated activations (unnormalized)
__device__ float          g_wr[IN_DIM * F_DIM];    // rotated weights (unnormalized)
__device__ __nv_bfloat16  g_xq[B_DIM * IN_DIM];    // quantized activations (bf16 ints) [M][K]
__device__ __nv_bfloat16  g_wqT[F_DIM * IN_DIM];   // quantized weights TRANSPOSED [N][K]
__device__ float          g_yr[B_DIM * F_DIM];     // GEMM result (float, exact ints)
__device__ int            g_maxx_bits;
__device__ int            g_maxw_bits;

// ===========================================================================
// Helpers
// ===========================================================================
__device__ __forceinline__ uint32_t smem_u32(const void* p) {
    uint32_t a;
    asm("{ .reg .u64 t; cvta.to.shared.u64 t, %1; cvt.u32.u64 %0, t; }" : "=r"(a) : "l"(p));
    return a;
}

__device__ __forceinline__ void cpasync16(uint32_t dst, const void* src) {
    asm volatile("cp.async.cg.shared.global [%0], [%1], 16;\n" :: "r"(dst), "l"(src));
}

// Swizzle<3,4,3>: XOR 16B-chunk bits [6:4] with 128B-line bits [9:7]
__device__ __forceinline__ uint32_t swz(uint32_t o) { return o ^ (((o >> 7) & 7) << 4); }

__device__ __forceinline__ void ldsm_x4(uint32_t r[4], uint32_t addr) {
    asm volatile("ldmatrix.sync.aligned.m8n8.x4.shared.b16 {%0,%1,%2,%3}, [%4];"
                 : "=r"(r[0]), "=r"(r[1]), "=r"(r[2]), "=r"(r[3]) : "r"(addr));
}

__device__ __forceinline__ void mma_bf16(float c[4], const uint32_t a[4], uint32_t b0, uint32_t b1) {
    asm volatile(
        "mma.sync.aligned.m16n8k16.row.col.f32.bf16.bf16.f32 "
        "{%0,%1,%2,%3}, {%4,%5,%6,%7}, {%8,%9}, {%0,%1,%2,%3};"
        : "+f"(c[0]), "+f"(c[1]), "+f"(c[2]), "+f"(c[3])
        : "r"(a[0]), "r"(a[1]), "r"(a[2]), "r"(a[3]), "r"(b0), "r"(b1));
}

// ===========================================================================
// WHT primitives
// ===========================================================================
__device__ __forceinline__ void wht64(float v[64]) {
#pragma unroll
    for (int s = 1; s < 64; s <<= 1) {
#pragma unroll
        for (int i = 0; i < 64; i++) {
            if ((i & s) == 0) {
                float a = v[i], b = v[i + s];
                v[i]     = a + b;
                v[i + s] = a - b;
            }
        }
    }
}

__global__ void init_kernel() {
    g_maxx_bits = 0;
    g_maxw_bits = 0;
}

// ---------------------------------------------------------------------------
// FUSED column-axis WHT-4096 (both radix-64 passes in one kernel).
// Block: 256 threads, 4 columns, full 4096 rows in 64 KB swizzled smem.
// Swizzle: phys = a ^ (((a>>8)&7)<<2)  (a = row*4 + c) -> both passes
// conflict-free; float4 groups preserved (bits 0-1 untouched).
// Pass 1: stride-1 groups (rows g*64+k); Pass 2: stride-64 (rows q+64k).
// Identical butterfly order to the previous two-kernel version.
// ---------------------------------------------------------------------------
#define CSWZ(a) ((a) ^ ((((a) >> 8) & 7) << 2))

template <bool DO_MAX, bool FINAL>
__global__ __launch_bounds__(256) void colwht_fused_kernel(const float* __restrict__ in,
                                                           float* __restrict__ out,
                                                           int ncols,
                                                           const float* __restrict__ bias) {
    extern __shared__ float sm[];   // 16384 floats (4096 rows x 4 cols), swizzled
    int tid  = threadIdx.x;
    int col0 = blockIdx.x * 4;

    // load: one float4 (4 cols of one row) per thread per iter
#pragma unroll
    for (int i = 0; i < 16; i++) {
        int row = tid + i * 256;
        float4 v = *(const float4*)&in[(size_t)row * ncols + col0];
        int a0 = row * 4;
        *(float4*)&sm[CSWZ(a0)] = v;
    }
    __syncthreads();

    int g = tid >> 2, c = tid & 3;   // owns (group g, local col c)
    float v[64];

    // pass 1: rows g*64 + k (stride 1)
#pragma unroll
    for (int k = 0; k < 64; k++) v[k] = sm[CSWZ((g * 64 + k) * 4 + c)];
    wht64(v);
#pragma unroll
    for (int k = 0; k < 64; k++) sm[CSWZ((g * 64 + k) * 4 + c)] = v[k];
    __syncthreads();

    // pass 2: rows q + 64k (stride 64); q == g
#pragma unroll
    for (int k = 0; k < 64; k++) v[k] = sm[CSWZ((g + 64 * k) * 4 + c)];
    wht64(v);

    if (DO_MAX) {
        float m = 0.f;
#pragma unroll
        for (int k = 0; k < 64; k++) m = fmaxf(m, fabsf(v[k]));
#pragma unroll
        for (int off = 16; off; off >>= 1)
            m = fmaxf(m, __shfl_xor_sync(0xffffffffu, m, off));
        if ((tid & 31) == 0) atomicMax(&g_maxx_bits, __float_as_int(m));
    }

    float scale = 1.f, bv = 0.f;
    if (FINAL) {
        float mx = __int_as_float(g_maxx_bits);
        float mw = __int_as_float(g_maxw_bits);
        scale = (mx / 127.f) * (mw / 127.f) * 0x1p-24f;
        bv    = bias[col0 + c];
    }
#pragma unroll
    for (int k = 0; k < 64; k++) {
        size_t idx = (size_t)(g + 64 * k) * ncols + col0 + c;
        out[idx] = FINAL ? (v[k] * scale + bv) : v[k];
    }
}

// ---------------------------------------------------------------------------
// Row-axis WHT (contiguous dim 4096), unchanged
// ---------------------------------------------------------------------------
template <bool DO_MAXW>
__global__ __launch_bounds__(128) void rowwht_kernel(const float* __restrict__ in,
                                                     float* __restrict__ out) {
    __shared__ float sm[2][4096];
    int g   = threadIdx.x >> 6;
    int t   = threadIdx.x & 63;
    int row = blockIdx.x * 2 + g;

    float v[64];
#pragma unroll
    for (int k = 0; k < 64; k++) v[k] = in[row * 4096 + t + (k << 6)];
    wht64(v);
#pragma unroll
    for (int k = 0; k < 64; k++) {
        int a  = t + (k << 6);
        int ph = a ^ ((a >> 6) & 31);
        sm[g][ph] = v[k];
    }
    __syncthreads();
#pragma unroll
    for (int k = 0; k < 64; k++) {
        int a  = (t << 6) + k;
        int ph = a ^ ((a >> 6) & 31);
        v[k] = sm[g][ph];
    }
    wht64(v);
#pragma unroll
    for (int k = 0; k < 64; k++) out[row * 4096 + (t << 6) + k] = v[k];

    if (DO_MAXW) {
        float m = 0.f;
#pragma unroll
        for (int k = 0; k < 64; k++) m = fmaxf(m, fabsf(v[k]));
#pragma unroll
        for (int off = 16; off; off >>= 1)
            m = fmaxf(m, __shfl_xor_sync(0xffffffffu, m, off));
        if ((threadIdx.x & 31) == 0) atomicMax(&g_maxw_bits, __float_as_int(m));
    }
}

// ===========================================================================
// Quantization (bf16 integer-valued outputs)
// ===========================================================================
__device__ __forceinline__ float stoch_q(float xv, float nv, float s) {
    float xs = xv / s;
    float f  = floorf(xs);
    float q  = f + ((nv < xs - f) ? 1.f : 0.f);
    return fminf(127.f, fmaxf(-127.f, q));
}

__global__ __launch_bounds__(256) void quantx_kernel(const float* __restrict__ xr,
                                                     const float* __restrict__ noise,
                                                     __nv_bfloat16* __restrict__ qo,
                                                     int n4) {
    int i = blockIdx.x * blockDim.x + threadIdx.x;
    if (i >= n4) return;
    float s = __int_as_float(g_maxx_bits) / 127.f;
    float4 x  = ((const float4*)xr)[i];
    float4 nz = ((const float4*)noise)[i];
    __nv_bfloat162 lo = __floats2bfloat162_rn(stoch_q(x.x, nz.x, s), stoch_q(x.y, nz.y, s));
    __nv_bfloat162 hi = __floats2bfloat162_rn(stoch_q(x.z, nz.z, s), stoch_q(x.w, nz.w, s));
    uint2 o;
    o.x = *(uint32_t*)&lo;
    o.y = *(uint32_t*)&hi;
    ((uint2*)qo)[i] = o;
}

// weights: quantize + transpose [IN][F] -> [F][IN] bf16 (K-major B operand)
__global__ __launch_bounds__(256) void quantw_transpose_kernel(const float* __restrict__ wr,
                                                               const float* __restrict__ noise,
                                                               __nv_bfloat16* __restrict__ qoT) {
    __shared__ __nv_bfloat16 t[32][33];
    float s = __int_as_float(g_maxw_bits) / 127.f;
    int x  = blockIdx.x * 32 + threadIdx.x;   // F index
    int y0 = blockIdx.y * 32;                 // IN base
#pragma unroll
    for (int j = 0; j < 4; j++) {
        int y   = y0 + threadIdx.y + j * 8;
        int idx = y * F_DIM + x;
        t[threadIdx.y + j * 8][threadIdx.x] = __float2bfloat16(stoch_q(wr[idx], noise[idx], s));
    }
    __syncthreads();
#pragma unroll
    for (int j = 0; j < 4; j++) {
        int fo = blockIdx.x * 32 + threadIdx.y + j * 8;
        qoT[(size_t)fo * IN_DIM + y0 + threadIdx.x] = t[threadIdx.x][threadIdx.y + j * 8];
    }
}

// ===========================================================================
// Pipelined bf16 GEMM (HMMA): C(float) = A[4096x2048] @ B^T  (B stored [N][K])
// CTA 128x256, 8 warps (2x4), warp tile 64x64, BK=64 (128B rows, swizzled),
// 4-stage cp.async, 1 CTA/SM.
// ===========================================================================
#define GBM 128
#define GBN 256
#define GBK 64
#define NSTAGE 4
#define KT (IN_DIM / GBK)                          // 32
#define A_STG (GBM * GBK * 2)                      // 16384
#define B_STG (GBN * GBK * 2)                      // 32768
#define STAGE_BYTES (A_STG + B_STG)                // 49152
#define GEMM_SMEM (NSTAGE * STAGE_BYTES)           // 196608

__global__ __launch_bounds__(256, 1) void gemm_bf16_kernel(const __nv_bfloat16* __restrict__ A,
                                                           const __nv_bfloat16* __restrict__ Bm,
                                                           float* __restrict__ C) {
    extern __shared__ char smem[];
    uint32_t sb = smem_u32(smem);
    int tid = threadIdx.x, warp = tid >> 5, lane = tid & 31;
    int bm = blockIdx.y * GBM, bn = blockIdx.x * GBN;
    int wm = (warp >> 2) * 64;   // 2 warps along M, tile 64
    int wn = (warp & 3) * 64;    // 4 warps along N, tile 64

    float acc[4][8][4];
#pragma unroll
    for (int i = 0; i < 4; i++)
#pragma unroll
        for (int j = 0; j < 8; j++)
#pragma unroll
            for (int k = 0; k < 4; k++) acc[i][j][k] = 0.f;

    auto load_stage = [&](int s, int ki) {
        uint32_t sA = sb + s * STAGE_BYTES;
        uint32_t sB = sA + A_STG;
        int k0 = ki * GBK;
#pragma unroll
        for (int j = 0; j < 4; j++) {           // A: 128 rows x 8 x 16B = 1024 chunks
            int cch = tid + j * 256;
            int row = cch >> 3, cc = cch & 7;
            cpasync16(sA + swz(row * 128 + cc * 16),
                      A + (size_t)(bm + row) * IN_DIM + k0 + cc * 8);
        }
#pragma unroll
        for (int j = 0; j < 8; j++) {           // B: 256 rows x 8 x 16B = 2048 chunks
            int cch = tid + j * 256;
            int row = cch >> 3, cc = cch & 7;
            cpasync16(sB + swz(row * 128 + cc * 16),
                      Bm + (size_t)(bn + row) * IN_DIM + k0 + cc * 8);
        }
        asm volatile("cp.async.commit_group;\n");
    };

    load_stage(0, 0);
    load_stage(1, 1);
    load_stage(2, 2);

    int rl = lane & 15, chh = (lane >> 4) * 16;
    for (int i = 0; i < KT; i++) {
        asm volatile("cp.async.wait_group 2;\n");   // stage i landed
        __syncthreads();                            // prev-iter reads done everywhere
        if (i + 3 < KT) load_stage((i + 3) & 3, i + 3);  // prefetch before compute

        uint32_t sA = sb + (i & 3) * STAGE_BYTES;
        uint32_t sB = sA + A_STG;
#pragma unroll
        for (int ks = 0; ks < 4; ks++) {            // 4 x k16
            uint32_t a[4][4], b[4][4];
#pragma unroll
            for (int mt = 0; mt < 4; mt++)
                ldsm_x4(a[mt], sA + swz((wm + mt * 16 + rl) * 128 + ks * 32 + chh));
#pragma unroll
            for (int ng = 0; ng < 4; ng++)
                ldsm_x4(b[ng], sB + swz((wn + ng * 16 + rl) * 128 + ks * 32 + chh));
#pragma unroll
            for (int mt = 0; mt < 4; mt++)
#pragma unroll
                for (int ng = 0; ng < 4; ng++) {
                    mma_bf16(acc[mt][2 * ng + 0], a[mt], b[ng][0], b[ng][2]);
                    mma_bf16(acc[mt][2 * ng + 1], a[mt], b[ng][1], b[ng][3]);
                }
        }
    }

    // Epilogue: accumulators already float (exact ints), direct stores
    float* outp = C + (size_t)bm * F_DIM + bn;
#pragma unroll
    for (int mt = 0; mt < 4; mt++)
#pragma unroll
        for (int nt = 0; nt < 8; nt++) {
            int row = wm + mt * 16 + (lane >> 2);
            int col = wn + nt * 8 + (lane & 3) * 2;
            *(float2*)&outp[(size_t)row * F_DIM + col] =
                make_float2(acc[mt][nt][0], acc[mt][nt][1]);
            *(float2*)&outp[(size_t)(row + 8) * F_DIM + col] =
                make_float2(acc[mt][nt][2], acc[mt][nt][3]);
        }
}

// ===========================================================================
// Host launcher
// ===========================================================================
extern "C" void kernel_launch(void* const* d_in, const int* in_sizes, int n_in,
                              void* d_out, int out_size) {
    const float* x       = (const float*)d_in[0];  // [4096, 2048]
    const float* w       = (const float*)d_in[1];  // [2048, 4096]
    const float* bias    = (const float*)d_in[2];  // [4096]
    const float* noise_x = (const float*)d_in[5];  // [4096, 2048]
    const float* noise_w = (const float*)d_in[6];  // [2048, 4096]
    float* out = (float*)d_out;                    // [4096, 4096]

    float*          xr_p = nullptr;
    float*          wr_p = nullptr;
    __nv_bfloat16*  xq_p = nullptr;
    __nv_bfloat16*  wq_p = nullptr;
    float*          yr_p = nullptr;
    cudaGetSymbolAddress((void**)&xr_p, g_xr);
    cudaGetSymbolAddress((void**)&wr_p, g_wr);
    cudaGetSymbolAddress((void**)&xq_p, g_xq);
    cudaGetSymbolAddress((void**)&wq_p, g_wqT);
    cudaGetSymbolAddress((void**)&yr_p, g_yr);

    const int CW_SMEM = 4096 * 4 * sizeof(float);  // 64 KB
    cudaFuncSetAttribute(gemm_bf16_kernel, cudaFuncAttributeMaxDynamicSharedMemorySize,
                         GEMM_SMEM);
    cudaFuncSetAttribute(colwht_fused_kernel<true, false>,
                         cudaFuncAttributeMaxDynamicSharedMemorySize, CW_SMEM);
    cudaFuncSetAttribute(colwht_fused_kernel<false, true>,
                         cudaFuncAttributeMaxDynamicSharedMemorySize, CW_SMEM);

    init_kernel<<<1, 1>>>();

    // xr = WHT_batch(x) (both radix-64 passes fused), with global max
    colwht_fused_kernel<true, false><<<IN_DIM / 4, 256, CW_SMEM>>>(x, xr_p, IN_DIM, nullptr);
    quantx_kernel<<<(B_DIM * IN_DIM / 4 + 255) / 256, 256>>>(xr_p, noise_x, xq_p,
                                                             B_DIM * IN_DIM / 4);

    // wr = WHT_features(w), fused max; quantize + transpose to [F][IN]
    rowwht_kernel<true><<<IN_DIM / 2, 128>>>(w, wr_p);
    quantw_transpose_kernel<<<dim3(F_DIM / 32, IN_DIM / 32), dim3(32, 8)>>>(wr_p, noise_w, wq_p);

    // pipelined bf16 HMMA GEMM -> float (exact integer arithmetic)
    gemm_bf16_kernel<<<dim3(F_DIM / GBN, B_DIM / GBM), 256, GEMM_SMEM>>>(xq_p, wq_p, yr_p);

    // inverse rotations: rows, then fused column pair with scale+bias -> out
    rowwht_kernel<false><<<B_DIM / 2, 128>>>(yr_p, yr_p);
    colwht_fused_kernel<false, true><<<F_DIM / 4, 256, CW_SMEM>>>(yr_p, out, F_DIM, bias);
}

// round 7
// speedup vs baseline: 1.4657x; 1.4657x over previous
#include <cuda_runtime.h>
#include <cuda_bf16.h>
#include <cstdint>

#define B_DIM 4096
#define IN_DIM 2048
#define F_DIM 4096

// ---------------------------------------------------------------------------
// Scratch (device globals: no allocation allowed)
// ---------------------------------------------------------------------------
__device__ float          g_xr[B_DIM * IN_DIM];    // rotated activations (unnormalized)
__device__ float          g_wr[IN_DIM * F_DIM];    // rotated weights (unnormalized)
__device__ __nv_bfloat16  g_xq[B_DIM * IN_DIM];    // quantized activations (bf16 ints) [M][K]
__device__ __nv_bfloat16  g_wqT[F_DIM * IN_DIM];   // quantized weights TRANSPOSED [N][K]
__device__ float          g_yr[B_DIM * F_DIM];     // GEMM result (float, exact ints)
__device__ int            g_maxx_bits;
__device__ int            g_maxw_bits;

// ===========================================================================
// Helpers
// ===========================================================================
__device__ __forceinline__ uint32_t smem_u32(const void* p) {
    uint32_t a;
    asm("{ .reg .u64 t; cvta.to.shared.u64 t, %1; cvt.u32.u64 %0, t; }" : "=r"(a) : "l"(p));
    return a;
}

__device__ __forceinline__ void cpasync16(uint32_t dst, const void* src) {
    asm volatile("cp.async.cg.shared.global [%0], [%1], 16;\n" :: "r"(dst), "l"(src));
}

// Swizzle<3,4,3>: XOR 16B-chunk bits [6:4] with 128B-line bits [9:7]
__device__ __forceinline__ uint32_t swz(uint32_t o) { return o ^ (((o >> 7) & 7) << 4); }

__device__ __forceinline__ void ldsm_x4(uint32_t r[4], uint32_t addr) {
    asm volatile("ldmatrix.sync.aligned.m8n8.x4.shared.b16 {%0,%1,%2,%3}, [%4];"
                 : "=r"(r[0]), "=r"(r[1]), "=r"(r[2]), "=r"(r[3]) : "r"(addr));
}

__device__ __forceinline__ void mma_bf16(float c[4], const uint32_t a[4], uint32_t b0, uint32_t b1) {
    asm volatile(
        "mma.sync.aligned.m16n8k16.row.col.f32.bf16.bf16.f32 "
        "{%0,%1,%2,%3}, {%4,%5,%6,%7}, {%8,%9}, {%0,%1,%2,%3};"
        : "+f"(c[0]), "+f"(c[1]), "+f"(c[2]), "+f"(c[3])
        : "r"(a[0]), "r"(a[1]), "r"(a[2]), "r"(a[3]), "r"(b0), "r"(b1));
}

// ===========================================================================
// WHT primitives
// ===========================================================================
__device__ __forceinline__ void wht64(float v[64]) {
#pragma unroll
    for (int s = 1; s < 64; s <<= 1) {
#pragma unroll
        for (int i = 0; i < 64; i++) {
            if ((i & s) == 0) {
                float a = v[i], b = v[i + s];
                v[i]     = a + b;
                v[i + s] = a - b;
            }
        }
    }
}

__global__ void init_kernel() {
    g_maxx_bits = 0;
    g_maxw_bits = 0;
}

// ---------------------------------------------------------------------------
// Column-axis WHT pass (round-5 version: fully coalesced, two launches)
// ---------------------------------------------------------------------------
template <int STRIDE, bool DO_MAX, bool FINAL>
__global__ __launch_bounds__(256) void colwht_kernel(const float* __restrict__ in,
                                                     float* __restrict__ out,
                                                     int ncols,
                                                     const float* __restrict__ bias) {
    int gtid = blockIdx.x * blockDim.x + threadIdx.x;
    int col  = gtid % ncols;
    int q    = gtid / ncols;
    int base = (STRIDE == 1) ? (q << 6) : q;

    float v[64];
#pragma unroll
    for (int b = 0; b < 64; b++) v[b] = in[(size_t)(base + b * STRIDE) * ncols + col];
    wht64(v);

    if (DO_MAX) {
        float m = 0.f;
#pragma unroll
        for (int b = 0; b < 64; b++) m = fmaxf(m, fabsf(v[b]));
#pragma unroll
        for (int off = 16; off; off >>= 1)
            m = fmaxf(m, __shfl_xor_sync(0xffffffffu, m, off));
        if ((threadIdx.x & 31) == 0) atomicMax(&g_maxx_bits, __float_as_int(m));
    }

    float scale = 1.f, bv = 0.f;
    if (FINAL) {
        float mx = __int_as_float(g_maxx_bits);
        float mw = __int_as_float(g_maxw_bits);
        scale = (mx / 127.f) * (mw / 127.f) * 0x1p-24f;
        bv    = bias[col];
    }
#pragma unroll
    for (int b = 0; b < 64; b++) {
        size_t r = base + b * STRIDE;
        out[r * ncols + col] = FINAL ? (v[b] * scale + bv) : v[b];
    }
}

// ---------------------------------------------------------------------------
// Row-axis WHT (contiguous dim 4096) with COALESCED writeout.
// Same butterflies as before; output restaged through smem so gmem stores
// are 128B/warp instead of 4B-per-32B-sector (8x amplification fixed).
// ---------------------------------------------------------------------------
template <bool DO_MAXW>
__global__ __launch_bounds__(128) void rowwht_kernel(const float* __restrict__ in,
                                                     float* __restrict__ out) {
    __shared__ float sm[2][4096];
    int g   = threadIdx.x >> 6;
    int t   = threadIdx.x & 63;
    int row = blockIdx.x * 2 + g;

    float v[64];
#pragma unroll
    for (int k = 0; k < 64; k++) v[k] = in[(size_t)row * 4096 + t + (k << 6)];
    wht64(v);
#pragma unroll
    for (int k = 0; k < 64; k++) {
        int a = t + (k << 6);
        sm[g][a ^ ((a >> 6) & 31)] = v[k];
    }
    __syncthreads();
#pragma unroll
    for (int k = 0; k < 64; k++) {
        int a = (t << 6) + k;
        v[k] = sm[g][a ^ ((a >> 6) & 31)];
    }
    wht64(v);

    if (DO_MAXW) {
        float m = 0.f;
#pragma unroll
        for (int k = 0; k < 64; k++) m = fmaxf(m, fabsf(v[k]));
#pragma unroll
        for (int off = 16; off; off >>= 1)
            m = fmaxf(m, __shfl_xor_sync(0xffffffffu, m, off));
        if ((threadIdx.x & 31) == 0) atomicMax(&g_maxw_bits, __float_as_int(m));
    }

    __syncthreads();  // pass-2 reads complete before overwrite
#pragma unroll
    for (int k = 0; k < 64; k++) {
        int a = (t << 6) + k;
        sm[g][a ^ ((a >> 6) & 31)] = v[k];   // conflict-free: bank = (k^t)&31
    }
    __syncthreads();

    // coalesced linear writeout: 128B per warp-store
    size_t base = (size_t)blockIdx.x * 2 * 4096;
#pragma unroll
    for (int i = 0; i < 64; i++) {
        int lin = threadIdx.x + i * 128;
        int gg  = lin >> 12;
        int a   = lin & 4095;
        out[base + lin] = sm[gg][a ^ ((a >> 6) & 31)];
    }
}

// ===========================================================================
// Quantization (bf16 integer-valued outputs)
// ===========================================================================
__device__ __forceinline__ float stoch_q(float xv, float nv, float s) {
    float xs = xv / s;
    float f  = floorf(xs);
    float q  = f + ((nv < xs - f) ? 1.f : 0.f);
    return fminf(127.f, fmaxf(-127.f, q));
}

__global__ __launch_bounds__(256) void quantx_kernel(const float* __restrict__ xr,
                                                     const float* __restrict__ noise,
                                                     __nv_bfloat16* __restrict__ qo,
                                                     int n4) {
    int i = blockIdx.x * blockDim.x + threadIdx.x;
    if (i >= n4) return;
    float s = __int_as_float(g_maxx_bits) / 127.f;
    float4 x  = ((const float4*)xr)[i];
    float4 nz = ((const float4*)noise)[i];
    __nv_bfloat162 lo = __floats2bfloat162_rn(stoch_q(x.x, nz.x, s), stoch_q(x.y, nz.y, s));
    __nv_bfloat162 hi = __floats2bfloat162_rn(stoch_q(x.z, nz.z, s), stoch_q(x.w, nz.w, s));
    uint2 o;
    o.x = *(uint32_t*)&lo;
    o.y = *(uint32_t*)&hi;
    ((uint2*)qo)[i] = o;
}

// weights: quantize + transpose [IN][F] -> [F][IN] bf16 (K-major B operand)
__global__ __launch_bounds__(256) void quantw_transpose_kernel(const float* __restrict__ wr,
                                                               const float* __restrict__ noise,
                                                               __nv_bfloat16* __restrict__ qoT) {
    __shared__ __nv_bfloat16 t[32][33];
    float s = __int_as_float(g_maxw_bits) / 127.f;
    int x  = blockIdx.x * 32 + threadIdx.x;   // F index
    int y0 = blockIdx.y * 32;                 // IN base
#pragma unroll
    for (int j = 0; j < 4; j++) {
        int y   = y0 + threadIdx.y + j * 8;
        int idx = y * F_DIM + x;
        t[threadIdx.y + j * 8][threadIdx.x] = __float2bfloat16(stoch_q(wr[idx], noise[idx], s));
    }
    __syncthreads();
#pragma unroll
    for (int j = 0; j < 4; j++) {
        int fo = blockIdx.x * 32 + threadIdx.y + j * 8;
        qoT[(size_t)fo * IN_DIM + y0 + threadIdx.x] = t[threadIdx.x][threadIdx.y + j * 8];
    }
}

// ===========================================================================
// Pipelined bf16 GEMM (HMMA), round-5 config: CTA 128x128, 8 warps (2x4),
// warp tile 64x32, BK=64 (128B rows, SW128), 3-stage cp.async, 2 CTAs/SM.
// ===========================================================================
#define GBM 128
#define GBN 128
#define GBK 64
#define NSTAGE 3
#define KT (IN_DIM / GBK)                          // 32
#define STAGE_BYTES ((GBM + GBN) * GBK * 2)        // 32768
#define GEMM_SMEM (NSTAGE * STAGE_BYTES)           // 98304

__global__ __launch_bounds__(256, 2) void gemm_bf16_kernel(const __nv_bfloat16* __restrict__ A,
                                                           const __nv_bfloat16* __restrict__ Bm,
                                                           float* __restrict__ C) {
    extern __shared__ char smem[];
    uint32_t sb = smem_u32(smem);
    int tid = threadIdx.x, warp = tid >> 5, lane = tid & 31;
    int bm = blockIdx.y * GBM, bn = blockIdx.x * GBN;
    int wm = (warp >> 2) * 64;   // 2 warps along M
    int wn = (warp & 3) * 32;    // 4 warps along N

    float acc[4][4][4];
#pragma unroll
    for (int i = 0; i < 4; i++)
#pragma unroll
        for (int j = 0; j < 4; j++)
#pragma unroll
            for (int k = 0; k < 4; k++) acc[i][j][k] = 0.f;

    auto load_stage = [&](int s, int ki) {
        uint32_t sA = sb + s * STAGE_BYTES;
        uint32_t sB = sA + GBM * GBK * 2;
        int k0 = ki * GBK;
#pragma unroll
        for (int j = 0; j < 4; j++) {
            int c = tid + j * 256;
            int row = c >> 3, cc = c & 7;
            cpasync16(sA + swz(row * 128 + cc * 16),
                      A + (size_t)(bm + row) * IN_DIM + k0 + cc * 8);
        }
#pragma unroll
        for (int j = 0; j < 4; j++) {
            int c = tid + j * 256;
            int row = c >> 3, cc = c & 7;
            cpasync16(sB + swz(row * 128 + cc * 16),
                      Bm + (size_t)(bn + row) * IN_DIM + k0 + cc * 8);
        }
        asm volatile("cp.async.commit_group;\n");
    };

    load_stage(0, 0);
    load_stage(1, 1);

    int rl = lane & 15, chh = (lane >> 4) * 16;
    int cur = 0;
    for (int i = 0; i < KT; i++) {
        asm volatile("cp.async.wait_group 1;\n");
        __syncthreads();
        if (i + 2 < KT) {
            int nxt = cur + 2; if (nxt >= NSTAGE) nxt -= NSTAGE;
            load_stage(nxt, i + 2);
        }

        uint32_t sA = sb + cur * STAGE_BYTES;
        uint32_t sB = sA + GBM * GBK * 2;
#pragma unroll
        for (int ks = 0; ks < 4; ks++) {
            uint32_t a[4][4], b[2][4];
#pragma unroll
            for (int mt = 0; mt < 4; mt++)
                ldsm_x4(a[mt], sA + swz((wm + mt * 16 + rl) * 128 + ks * 32 + chh));
#pragma unroll
            for (int ng = 0; ng < 2; ng++)
                ldsm_x4(b[ng], sB + swz((wn + ng * 16 + rl) * 128 + ks * 32 + chh));
#pragma unroll
            for (int mt = 0; mt < 4; mt++)
#pragma unroll
                for (int ng = 0; ng < 2; ng++) {
                    mma_bf16(acc[mt][2 * ng + 0], a[mt], b[ng][0], b[ng][2]);
                    mma_bf16(acc[mt][2 * ng + 1], a[mt], b[ng][1], b[ng][3]);
                }
        }
        cur = (cur + 1 == NSTAGE) ? 0 : cur + 1;
    }

    float* outp = C + (size_t)bm * F_DIM + bn;
#pragma unroll
    for (int mt = 0; mt < 4; mt++)
#pragma unroll
        for (int nt = 0; nt < 4; nt++) {
            int row = wm + mt * 16 + (lane >> 2);
            int col = wn + nt * 8 + (lane & 3) * 2;
            *(float2*)&outp[(size_t)row * F_DIM + col] =
                make_float2(acc[mt][nt][0], acc[mt][nt][1]);
            *(float2*)&outp[(size_t)(row + 8) * F_DIM + col] =
                make_float2(acc[mt][nt][2], acc[mt][nt][3]);
        }
}

// ===========================================================================
// Host launcher
// ===========================================================================
extern "C" void kernel_launch(void* const* d_in, const int* in_sizes, int n_in,
                              void* d_out, int out_size) {
    const float* x       = (const float*)d_in[0];  // [4096, 2048]
    const float* w       = (const float*)d_in[1];  // [2048, 4096]
    const float* bias    = (const float*)d_in[2];  // [4096]
    const float* noise_x = (const float*)d_in[5];  // [4096, 2048]
    const float* noise_w = (const float*)d_in[6];  // [2048, 4096]
    float* out = (float*)d_out;                    // [4096, 4096]

    float*          xr_p = nullptr;
    float*          wr_p = nullptr;
    __nv_bfloat16*  xq_p = nullptr;
    __nv_bfloat16*  wq_p = nullptr;
    float*          yr_p = nullptr;
    cudaGetSymbolAddress((void**)&xr_p, g_xr);
    cudaGetSymbolAddress((void**)&wr_p, g_wr);
    cudaGetSymbolAddress((void**)&xq_p, g_xq);
    cudaGetSymbolAddress((void**)&wq_p, g_wqT);
    cudaGetSymbolAddress((void**)&yr_p, g_yr);

    cudaFuncSetAttribute(gemm_bf16_kernel, cudaFuncAttributeMaxDynamicSharedMemorySize,
                         GEMM_SMEM);

    init_kernel<<<1, 1>>>();

    // xr = WHT_batch(x) (unnormalized), fused max on second pass
    colwht_kernel<1, false, false><<<(64 * IN_DIM) / 256, 256>>>(x, xr_p, IN_DIM, nullptr);
    colwht_kernel<64, true, false><<<(64 * IN_DIM) / 256, 256>>>(xr_p, xr_p, IN_DIM, nullptr);
    quantx_kernel<<<(B_DIM * IN_DIM / 4 + 255) / 256, 256>>>(xr_p, noise_x, xq_p,
                                                             B_DIM * IN_DIM / 4);

    // wr = WHT_features(w), fused max; quantize + transpose to [F][IN]
    rowwht_kernel<true><<<IN_DIM / 2, 128>>>(w, wr_p);
    quantw_transpose_kernel<<<dim3(F_DIM / 32, IN_DIM / 32), dim3(32, 8)>>>(wr_p, noise_w, wq_p);

    // pipelined bf16 HMMA GEMM -> float (exact integer arithmetic)
    gemm_bf16_kernel<<<dim3(F_DIM / GBN, B_DIM / GBM), 256, GEMM_SMEM>>>(xq_p, wq_p, yr_p);

    // inverse rotations: rows, then columns (scale+bias fused into last pass)
    rowwht_kernel<false><<<B_DIM / 2, 128>>>(yr_p, yr_p);
    colwht_kernel<1, false, false><<<(64 * F_DIM) / 256, 256>>>(yr_p, yr_p, F_DIM, nullptr);
    colwht_kernel<64, false, true><<<(64 * F_DIM) / 256, 256>>>(yr_p, out, F_DIM, bias);
}

// round 8
// speedup vs baseline: 1.5251x; 1.0406x over previous
#include <cuda_runtime.h>
#include <cuda_bf16.h>
#include <cstdint>

#define B_DIM 4096
#define IN_DIM 2048
#define F_DIM 4096

// ---------------------------------------------------------------------------
// Scratch (device globals: no allocation allowed)
// ---------------------------------------------------------------------------
__device__ float          g_xr[B_DIM * IN_DIM];    // rotated activations (unnormalized)
__device__ float          g_wr[IN_DIM * F_DIM];    // rotated weights (unnormalized)
__device__ __nv_bfloat16  g_xq[B_DIM * IN_DIM];    // quantized activations (bf16 ints) [M][K]
__device__ __nv_bfloat16  g_wqT[F_DIM * IN_DIM];   // quantized weights TRANSPOSED [N][K]
__device__ float          g_yr[B_DIM * F_DIM];     // GEMM result (float, exact ints)
__device__ int            g_maxx_bits;
__device__ int            g_maxw_bits;

// ===========================================================================
// Helpers
// ===========================================================================
__device__ __forceinline__ uint32_t smem_u32(const void* p) {
    uint32_t a;
    asm("{ .reg .u64 t; cvta.to.shared.u64 t, %1; cvt.u32.u64 %0, t; }" : "=r"(a) : "l"(p));
    return a;
}

__device__ __forceinline__ void cpasync16(uint32_t dst, const void* src) {
    asm volatile("cp.async.cg.shared.global [%0], [%1], 16;\n" :: "r"(dst), "l"(src));
}

// Swizzle<3,4,3>: XOR 16B-chunk bits [6:4] with 128B-line bits [9:7]
__device__ __forceinline__ uint32_t swz(uint32_t o) { return o ^ (((o >> 7) & 7) << 4); }

__device__ __forceinline__ void ldsm_x4(uint32_t r[4], uint32_t addr) {
    asm volatile("ldmatrix.sync.aligned.m8n8.x4.shared.b16 {%0,%1,%2,%3}, [%4];"
                 : "=r"(r[0]), "=r"(r[1]), "=r"(r[2]), "=r"(r[3]) : "r"(addr));
}

__device__ __forceinline__ void mma_bf16(float c[4], const uint32_t a[4], uint32_t b0, uint32_t b1) {
    asm volatile(
        "mma.sync.aligned.m16n8k16.row.col.f32.bf16.bf16.f32 "
        "{%0,%1,%2,%3}, {%4,%5,%6,%7}, {%8,%9}, {%0,%1,%2,%3};"
        : "+f"(c[0]), "+f"(c[1]), "+f"(c[2]), "+f"(c[3])
        : "r"(a[0]), "r"(a[1]), "r"(a[2]), "r"(a[3]), "r"(b0), "r"(b1));
}

// ===========================================================================
// WHT primitives
// ===========================================================================
__device__ __forceinline__ void wht64(float v[64]) {
#pragma unroll
    for (int s = 1; s < 64; s <<= 1) {
#pragma unroll
        for (int i = 0; i < 64; i++) {
            if ((i & s) == 0) {
                float a = v[i], b = v[i + s];
                v[i]     = a + b;
                v[i + s] = a - b;
            }
        }
    }
}

__global__ void init_kernel() {
    g_maxx_bits = 0;
    g_maxw_bits = 0;
}

// ---------------------------------------------------------------------------
// FUSED column-axis WHT-4096: both radix-64 passes in one kernel.
// Block: 512 threads, 8 columns, all 4096 rows resident in 128 KB smem.
// Swizzle FSWZ keeps float4 IO intact (bits 0-1 untouched) and makes both
// the stride-1 and stride-64 smem access patterns bank-conflict-free.
// All gmem accesses are 32B-aligned 32B runs -> 100% sector utilization.
// Butterfly order identical to the unfused pair -> bit-identical results.
// ---------------------------------------------------------------------------
#define FSWZ(a) ((a) ^ ((((a) >> 9) & 3) << 3))

template <bool DO_MAX, bool FINAL>
__global__ __launch_bounds__(512) void colwht_fused8_kernel(const float* __restrict__ in,
                                                            float* __restrict__ out,
                                                            int ncols,
                                                            const float* __restrict__ bias) {
    extern __shared__ float sm[];   // 4096 rows x 8 cols, swizzled (128 KB)
    int tid  = threadIdx.x;
    int col0 = blockIdx.x * 8;

    // Load: 8192 float4s (2 per row), fully coalesced (32B runs per row)
#pragma unroll
    for (int j = 0; j < 16; j++) {
        int i = tid + j * 512;             // float4 index
        int r = i >> 1, q = i & 1;
        float4 v = *(const float4*)&in[(size_t)r * ncols + col0 + q * 4];
        *(float4*)&sm[FSWZ(r * 8 + q * 4)] = v;
    }
    __syncthreads();

    int g = tid >> 3, c = tid & 7;         // thread owns (group g, local col c)
    float v[64];

    // pass 1: rows g*64 + k (stride 1)
#pragma unroll
    for (int k = 0; k < 64; k++) v[k] = sm[FSWZ((g * 64 + k) * 8 + c)];
    wht64(v);
#pragma unroll
    for (int k = 0; k < 64; k++) sm[FSWZ((g * 64 + k) * 8 + c)] = v[k];
    __syncthreads();

    // pass 2: rows g + 64k (stride 64)
#pragma unroll
    for (int k = 0; k < 64; k++) v[k] = sm[FSWZ((g + 64 * k) * 8 + c)];
    wht64(v);

    if (DO_MAX) {
        float m = 0.f;
#pragma unroll
        for (int k = 0; k < 64; k++) m = fmaxf(m, fabsf(v[k]));
#pragma unroll
        for (int off = 16; off; off >>= 1)
            m = fmaxf(m, __shfl_xor_sync(0xffffffffu, m, off));
        if ((tid & 31) == 0) atomicMax(&g_maxx_bits, __float_as_int(m));
    }

    float scale = 1.f, bv = 0.f;
    if (FINAL) {
        float mx = __int_as_float(g_maxx_bits);
        float mw = __int_as_float(g_maxw_bits);
        scale = (mx / 127.f) * (mw / 127.f) * 0x1p-24f;
        bv    = bias[col0 + c];
    }
    // writeout: per warp 4 rows x 8 consecutive floats = 32B runs
#pragma unroll
    for (int k = 0; k < 64; k++) {
        size_t idx = (size_t)(g + 64 * k) * ncols + col0 + c;
        out[idx] = FINAL ? (v[k] * scale + bv) : v[k];
    }
}

// ---------------------------------------------------------------------------
// Row-axis WHT (contiguous dim 4096) with coalesced writeout (round-7)
// ---------------------------------------------------------------------------
template <bool DO_MAXW>
__global__ __launch_bounds__(128) void rowwht_kernel(const float* __restrict__ in,
                                                     float* __restrict__ out) {
    __shared__ float sm[2][4096];
    int g   = threadIdx.x >> 6;
    int t   = threadIdx.x & 63;
    int row = blockIdx.x * 2 + g;

    float v[64];
#pragma unroll
    for (int k = 0; k < 64; k++) v[k] = in[(size_t)row * 4096 + t + (k << 6)];
    wht64(v);
#pragma unroll
    for (int k = 0; k < 64; k++) {
        int a = t + (k << 6);
        sm[g][a ^ ((a >> 6) & 31)] = v[k];
    }
    __syncthreads();
#pragma unroll
    for (int k = 0; k < 64; k++) {
        int a = (t << 6) + k;
        v[k] = sm[g][a ^ ((a >> 6) & 31)];
    }
    wht64(v);

    if (DO_MAXW) {
        float m = 0.f;
#pragma unroll
        for (int k = 0; k < 64; k++) m = fmaxf(m, fabsf(v[k]));
#pragma unroll
        for (int off = 16; off; off >>= 1)
            m = fmaxf(m, __shfl_xor_sync(0xffffffffu, m, off));
        if ((threadIdx.x & 31) == 0) atomicMax(&g_maxw_bits, __float_as_int(m));
    }

    __syncthreads();
#pragma unroll
    for (int k = 0; k < 64; k++) {
        int a = (t << 6) + k;
        sm[g][a ^ ((a >> 6) & 31)] = v[k];
    }
    __syncthreads();

    size_t base = (size_t)blockIdx.x * 2 * 4096;
#pragma unroll
    for (int i = 0; i < 64; i++) {
        int lin = threadIdx.x + i * 128;
        int gg  = lin >> 12;
        int a   = lin & 4095;
        out[base + lin] = sm[gg][a ^ ((a >> 6) & 31)];
    }
}

// ===========================================================================
// Quantization (bf16 integer-valued outputs)
// ===========================================================================
__device__ __forceinline__ float stoch_q(float xv, float nv, float s) {
    float xs = xv / s;
    float f  = floorf(xs);
    float q  = f + ((nv < xs - f) ? 1.f : 0.f);
    return fminf(127.f, fmaxf(-127.f, q));
}

__global__ __launch_bounds__(256) void quantx_kernel(const float* __restrict__ xr,
                                                     const float* __restrict__ noise,
                                                     __nv_bfloat16* __restrict__ qo,
                                                     int n4) {
    int i = blockIdx.x * blockDim.x + threadIdx.x;
    if (i >= n4) return;
    float s = __int_as_float(g_maxx_bits) / 127.f;
    float4 x  = ((const float4*)xr)[i];
    float4 nz = ((const float4*)noise)[i];
    __nv_bfloat162 lo = __floats2bfloat162_rn(stoch_q(x.x, nz.x, s), stoch_q(x.y, nz.y, s));
    __nv_bfloat162 hi = __floats2bfloat162_rn(stoch_q(x.z, nz.z, s), stoch_q(x.w, nz.w, s));
    uint2 o;
    o.x = *(uint32_t*)&lo;
    o.y = *(uint32_t*)&hi;
    ((uint2*)qo)[i] = o;
}

// weights: quantize + transpose [IN][F] -> [F][IN] bf16 (K-major B operand)
__global__ __launch_bounds__(256) void quantw_transpose_kernel(const float* __restrict__ wr,
                                                               const float* __restrict__ noise,
                                                               __nv_bfloat16* __restrict__ qoT) {
    __shared__ __nv_bfloat16 t[32][33];
    float s = __int_as_float(g_maxw_bits) / 127.f;
    int x  = blockIdx.x * 32 + threadIdx.x;   // F index
    int y0 = blockIdx.y * 32;                 // IN base
#pragma unroll
    for (int j = 0; j < 4; j++) {
        int y   = y0 + threadIdx.y + j * 8;
        int idx = y * F_DIM + x;
        t[threadIdx.y + j * 8][threadIdx.x] = __float2bfloat16(stoch_q(wr[idx], noise[idx], s));
    }
    __syncthreads();
#pragma unroll
    for (int j = 0; j < 4; j++) {
        int fo = blockIdx.x * 32 + threadIdx.y + j * 8;
        qoT[(size_t)fo * IN_DIM + y0 + threadIdx.x] = t[threadIdx.x][threadIdx.y + j * 8];
    }
}

// ===========================================================================
// Pipelined bf16 GEMM (HMMA), round-5/7 config: CTA 128x128, 8 warps (2x4),
// warp tile 64x32, BK=64 (128B rows, SW128), 3-stage cp.async, 2 CTAs/SM.
// ===========================================================================
#define GBM 128
#define GBN 128
#define GBK 64
#define NSTAGE 3
#define KT (IN_DIM / GBK)                          // 32
#define STAGE_BYTES ((GBM + GBN) * GBK * 2)        // 32768
#define GEMM_SMEM (NSTAGE * STAGE_BYTES)           // 98304

__global__ __launch_bounds__(256, 2) void gemm_bf16_kernel(const __nv_bfloat16* __restrict__ A,
                                                           const __nv_bfloat16* __restrict__ Bm,
                                                           float* __restrict__ C) {
    extern __shared__ char smem[];
    uint32_t sb = smem_u32(smem);
    int tid = threadIdx.x, warp = tid >> 5, lane = tid & 31;
    int bm = blockIdx.y * GBM, bn = blockIdx.x * GBN;
    int wm = (warp >> 2) * 64;   // 2 warps along M
    int wn = (warp & 3) * 32;    // 4 warps along N

    float acc[4][4][4];
#pragma unroll
    for (int i = 0; i < 4; i++)
#pragma unroll
        for (int j = 0; j < 4; j++)
#pragma unroll
            for (int k = 0; k < 4; k++) acc[i][j][k] = 0.f;

    auto load_stage = [&](int s, int ki) {
        uint32_t sA = sb + s * STAGE_BYTES;
        uint32_t sB = sA + GBM * GBK * 2;
        int k0 = ki * GBK;
#pragma unroll
        for (int j = 0; j < 4; j++) {
            int c = tid + j * 256;
            int row = c >> 3, cc = c & 7;
            cpasync16(sA + swz(row * 128 + cc * 16),
                      A + (size_t)(bm + row) * IN_DIM + k0 + cc * 8);
        }
#pragma unroll
        for (int j = 0; j < 4; j++) {
            int c = tid + j * 256;
            int row = c >> 3, cc = c & 7;
            cpasync16(sB + swz(row * 128 + cc * 16),
                      Bm + (size_t)(bn + row) * IN_DIM + k0 + cc * 8);
        }
        asm volatile("cp.async.commit_group;\n");
    };

    load_stage(0, 0);
    load_stage(1, 1);

    int rl = lane & 15, chh = (lane >> 4) * 16;
    int cur = 0;
    for (int i = 0; i < KT; i++) {
        asm volatile("cp.async.wait_group 1;\n");
        __syncthreads();
        if (i + 2 < KT) {
            int nxt = cur + 2; if (nxt >= NSTAGE) nxt -= NSTAGE;
            load_stage(nxt, i + 2);
        }

        uint32_t sA = sb + cur * STAGE_BYTES;
        uint32_t sB = sA + GBM * GBK * 2;
#pragma unroll
        for (int ks = 0; ks < 4; ks++) {
            uint32_t a[4][4], b[2][4];
#pragma unroll
            for (int mt = 0; mt < 4; mt++)
                ldsm_x4(a[mt], sA + swz((wm + mt * 16 + rl) * 128 + ks * 32 + chh));
#pragma unroll
            for (int ng = 0; ng < 2; ng++)
                ldsm_x4(b[ng], sB + swz((wn + ng * 16 + rl) * 128 + ks * 32 + chh));
#pragma unroll
            for (int mt = 0; mt < 4; mt++)
#pragma unroll
                for (int ng = 0; ng < 2; ng++) {
                    mma_bf16(acc[mt][2 * ng + 0], a[mt], b[ng][0], b[ng][2]);
                    mma_bf16(acc[mt][2 * ng + 1], a[mt], b[ng][1], b[ng][3]);
                }
        }
        cur = (cur + 1 == NSTAGE) ? 0 : cur + 1;
    }

    float* outp = C + (size_t)bm * F_DIM + bn;
#pragma unroll
    for (int mt = 0; mt < 4; mt++)
#pragma unroll
        for (int nt = 0; nt < 4; nt++) {
            int row = wm + mt * 16 + (lane >> 2);
            int col = wn + nt * 8 + (lane & 3) * 2;
            *(float2*)&outp[(size_t)row * F_DIM + col] =
                make_float2(acc[mt][nt][0], acc[mt][nt][1]);
            *(float2*)&outp[(size_t)(row + 8) * F_DIM + col] =
                make_float2(acc[mt][nt][2], acc[mt][nt][3]);
        }
}

// ===========================================================================
// Host launcher
// ===========================================================================
extern "C" void kernel_launch(void* const* d_in, const int* in_sizes, int n_in,
                              void* d_out, int out_size) {
    const float* x       = (const float*)d_in[0];  // [4096, 2048]
    const float* w       = (const float*)d_in[1];  // [2048, 4096]
    const float* bias    = (const float*)d_in[2];  // [4096]
    const float* noise_x = (const float*)d_in[5];  // [4096, 2048]
    const float* noise_w = (const float*)d_in[6];  // [2048, 4096]
    float* out = (float*)d_out;                    // [4096, 4096]

    float*          xr_p = nullptr;
    float*          wr_p = nullptr;
    __nv_bfloat16*  xq_p = nullptr;
    __nv_bfloat16*  wq_p = nullptr;
    float*          yr_p = nullptr;
    cudaGetSymbolAddress((void**)&xr_p, g_xr);
    cudaGetSymbolAddress((void**)&wr_p, g_wr);
    cudaGetSymbolAddress((void**)&xq_p, g_xq);
    cudaGetSymbolAddress((void**)&wq_p, g_wqT);
    cudaGetSymbolAddress((void**)&yr_p, g_yr);

    const int CW_SMEM = 4096 * 8 * sizeof(float);  // 128 KB
    cudaFuncSetAttribute(gemm_bf16_kernel, cudaFuncAttributeMaxDynamicSharedMemorySize,
                         GEMM_SMEM);
    cudaFuncSetAttribute(colwht_fused8_kernel<true, false>,
                         cudaFuncAttributeMaxDynamicSharedMemorySize, CW_SMEM);
    cudaFuncSetAttribute(colwht_fused8_kernel<false, true>,
                         cudaFuncAttributeMaxDynamicSharedMemorySize, CW_SMEM);

    init_kernel<<<1, 1>>>();

    // xr = WHT_batch(x): both radix-64 passes fused, with global max
    colwht_fused8_kernel<true, false><<<IN_DIM / 8, 512, CW_SMEM>>>(x, xr_p, IN_DIM, nullptr);
    quantx_kernel<<<(B_DIM * IN_DIM / 4 + 255) / 256, 256>>>(xr_p, noise_x, xq_p,
                                                             B_DIM * IN_DIM / 4);

    // wr = WHT_features(w), fused max; quantize + transpose to [F][IN]
    rowwht_kernel<true><<<IN_DIM / 2, 128>>>(w, wr_p);
    quantw_transpose_kernel<<<dim3(F_DIM / 32, IN_DIM / 32), dim3(32, 8)>>>(wr_p, noise_w, wq_p);

    // pipelined bf16 HMMA GEMM -> float (exact integer arithmetic)
    gemm_bf16_kernel<<<dim3(F_DIM / GBN, B_DIM / GBM), 256, GEMM_SMEM>>>(xq_p, wq_p, yr_p);

    // inverse rotations: rows, then fused column pair with scale+bias -> out
    rowwht_kernel<false><<<B_DIM / 2, 128>>>(yr_p, yr_p);
    colwht_fused8_kernel<false, true><<<F_DIM / 8, 512, CW_SMEM>>>(yr_p, out, F_DIM, bias);
}